// round 3
// baseline (speedup 1.0000x reference)
#include <cuda_runtime.h>
#include <cuda_bf16.h>
#include <math_constants.h>

// Problem constants
#define NB      16         // batch
#define CDIM    256        // embedding dim
#define HW      1024       // 32*32
#define NPTS    16384      // NB*HW
#define KCODES  8192

// Main kernel tiling
#define BM      64
#define BN      128
#define DCHUNK  32
#define XSTR    68         // BM + 4 pad (keeps 16B alignment, spreads banks)
#define ESTR    132        // BN + 4 pad

// Output layout (floats), tuple flattened in order:
// encoded_flat (N*C) | quantized_flat (N*C) | indices (N) | quantized (N*C)
#define OFF_ENC   0
#define OFF_QF    (NPTS * CDIM)
#define OFF_IDX   (2 * NPTS * CDIM)
#define OFF_QUANT (2 * NPTS * CDIM + NPTS)

__device__ int   g_idx[NPTS];
__device__ float g_half_esq[KCODES];

// ---------------------------------------------------------------------------
// half_esq[k] = 0.5 * sum_d E[k][d]^2
// ---------------------------------------------------------------------------
__global__ void esq_kernel(const float* __restrict__ E) {
    int k = blockIdx.x * blockDim.x + threadIdx.x;
    const float4* p = (const float4*)(E + (size_t)k * CDIM);
    float s = 0.f;
#pragma unroll
    for (int i = 0; i < CDIM / 4; ++i) {
        float4 v = p[i];
        s += v.x * v.x + v.y * v.y + v.z * v.z + v.w * v.w;
    }
    g_half_esq[k] = 0.5f * s;
}

// ---------------------------------------------------------------------------
// Batched transpose: in [B][R][C] -> out [B][C][R]   (32x32 tiles)
// ---------------------------------------------------------------------------
__global__ void transpose_kernel(const float* __restrict__ in,
                                 float* __restrict__ out, int R, int C) {
    __shared__ float tile[32][33];
    int b  = blockIdx.z;
    int c0 = blockIdx.x * 32;
    int r0 = blockIdx.y * 32;
    const float* pin = in  + (size_t)b * R * C;
    float*       pout = out + (size_t)b * R * C;
    int tx = threadIdx.x, ty = threadIdx.y;   // 32 x 8
#pragma unroll
    for (int i = 0; i < 32; i += 8)
        tile[ty + i][tx] = pin[(size_t)(r0 + ty + i) * C + c0 + tx];
    __syncthreads();
#pragma unroll
    for (int i = 0; i < 32; i += 8)
        pout[(size_t)(c0 + ty + i) * R + r0 + tx] = tile[tx][ty + i];
}

// ---------------------------------------------------------------------------
// Fused GEMM + argmax:
//   score[n][k] = x_n . e_k - half_esq[k];  g_idx[n] = argmax_k score
// BM=64 x-rows cached fully in SMEM (all D), loop K in BN=128 tiles,
// D chunked by 32. 256 threads, 4x8 micro-tile (ty owns 4 rows, tx owns
// n = {tx*4..tx*4+3} U {64+tx*4..64+tx*4+3}).
// ---------------------------------------------------------------------------
__global__ __launch_bounds__(256, 2)
void argmax_kernel(const float* __restrict__ X, const float* __restrict__ E,
                   float* __restrict__ idxf_out) {
    extern __shared__ float smem[];
    float* xs    = smem;                    // [256][XSTR]
    float* es    = xs + CDIM * XSTR;        // [32][ESTR]
    float* hs    = es + DCHUNK * ESTR;      // [128]
    float* red_s = hs + BN;                 // [64][16]
    int*   red_i = (int*)(red_s + BM * 16); // [64][16]

    const int tid = threadIdx.x;
    const int tx  = tid & 15;
    const int ty  = tid >> 4;
    const int tx4 = tx * 4;
    const int ty4 = ty * 4;
    const int bm  = blockIdx.x * BM;

    // Stage X tile: 64 rows x 256 d, stored transposed xs[d][m]
#pragma unroll
    for (int it = 0; it < (BM * CDIM / 4) / 256; ++it) {
        int i  = tid + it * 256;
        int m  = i >> 6;          // /(CDIM/4)
        int d4 = i & 63;
        float4 v = *(const float4*)(X + (size_t)(bm + m) * CDIM + d4 * 4);
        float* p = xs + (d4 * 4) * XSTR + m;
        p[0] = v.x; p[XSTR] = v.y; p[2 * XSTR] = v.z; p[3 * XSTR] = v.w;
    }

    float best[4];
    int   bidx[4];
#pragma unroll
    for (int r = 0; r < 4; ++r) { best[r] = -CUDART_INF_F; bidx[r] = 0x7FFFFFFF; }

    for (int k0 = 0; k0 < KCODES; k0 += BN) {
        __syncthreads();                      // prev epilogue done reading hs
        if (tid < BN) hs[tid] = g_half_esq[k0 + tid];

        float acc[4][8];
#pragma unroll
        for (int r = 0; r < 4; ++r)
#pragma unroll
            for (int c = 0; c < 8; ++c) acc[r][c] = 0.f;

        for (int dc = 0; dc < CDIM; dc += DCHUNK) {
            __syncthreads();                  // prev chunk consumers done
            // load E tile chunk: BN rows x 32 d, transposed into es[d][n]
#pragma unroll
            for (int it = 0; it < (BN * DCHUNK / 4) / 256; ++it) {
                int i  = tid + it * 256;
                int kk = i >> 3;
                int d4 = i & 7;
                float4 v = *(const float4*)(E + (size_t)(k0 + kk) * CDIM + dc + d4 * 4);
                float* p = es + (d4 * 4) * ESTR + kk;
                p[0] = v.x; p[ESTR] = v.y; p[2 * ESTR] = v.z; p[3 * ESTR] = v.w;
            }
            __syncthreads();

#pragma unroll
            for (int d = 0; d < DCHUNK; ++d) {
                float4 a  = *(const float4*)(xs + (dc + d) * XSTR + ty4);
                const float* ep = es + d * ESTR + tx4;
                float4 b0 = *(const float4*)(ep);
                float4 b1 = *(const float4*)(ep + 64);
                float av[4] = {a.x, a.y, a.z, a.w};
                float bv[8] = {b0.x, b0.y, b0.z, b0.w, b1.x, b1.y, b1.z, b1.w};
#pragma unroll
                for (int r = 0; r < 4; ++r)
#pragma unroll
                    for (int c = 0; c < 8; ++c)
                        acc[r][c] += av[r] * bv[c];
            }
        }

        // running argmax update (argmin dist == argmax score; ties -> lower k)
#pragma unroll
        for (int c = 0; c < 8; ++c) {
            int nl = (c < 4) ? (tx4 + c) : (64 + tx4 + c - 4);
            float h = hs[nl];
            int   k = k0 + nl;
#pragma unroll
            for (int r = 0; r < 4; ++r) {
                float s = acc[r][c] - h;
                if (s > best[r] || (s == best[r] && k < bidx[r])) {
                    best[r] = s; bidx[r] = k;
                }
            }
        }
    }

    // cross-thread reduce: 16 tx threads per row
    __syncthreads();
#pragma unroll
    for (int r = 0; r < 4; ++r) {
        red_s[(ty4 + r) * 16 + tx] = best[r];
        red_i[(ty4 + r) * 16 + tx] = bidx[r];
    }
    __syncthreads();
    if (tid < BM) {
        float bs = red_s[tid * 16];
        int   bi = red_i[tid * 16];
#pragma unroll
        for (int j = 1; j < 16; ++j) {
            float s = red_s[tid * 16 + j];
            int   k = red_i[tid * 16 + j];
            if (s > bs || (s == bs && k < bi)) { bs = s; bi = k; }
        }
        int n = bm + tid;
        g_idx[n] = bi;
        idxf_out[n] = (float)bi;
    }
}

// ---------------------------------------------------------------------------
// quantized_flat[n] = enc[n] + (E[idx[n]] - enc[n])   (STE value)
// ---------------------------------------------------------------------------
__global__ void gather_kernel(const float* __restrict__ enc,
                              const float* __restrict__ E,
                              float* __restrict__ qflat) {
    int t = blockIdx.x * blockDim.x + threadIdx.x;   // N * (CDIM/4) threads
    int n = t >> 6;
    int j = t & 63;
    int idx = g_idx[n];
    float4 x = *(const float4*)(enc + (size_t)n * CDIM + j * 4);
    float4 e = *(const float4*)(E + (size_t)idx * CDIM + j * 4);
    float4 q;
    q.x = x.x + (e.x - x.x);
    q.y = x.y + (e.y - x.y);
    q.z = x.z + (e.z - x.z);
    q.w = x.w + (e.w - x.w);
    *(float4*)(qflat + (size_t)n * CDIM + j * 4) = q;
}

// ---------------------------------------------------------------------------
extern "C" void kernel_launch(void* const* d_in, const int* in_sizes, int n_in,
                              void* d_out, int out_size) {
    const float* z   = (const float*)d_in[0];   // (16, 256, 32, 32)
    const float* emb = (const float*)d_in[1];   // (8192, 256)
    float* out   = (float*)d_out;
    float* enc   = out + OFF_ENC;
    float* qflat = out + OFF_QF;
    float* idxf  = out + OFF_IDX;
    float* quant = out + OFF_QUANT;

    const int smem_bytes =
        (CDIM * XSTR + DCHUNK * ESTR + BN + BM * 16 * 2) * (int)sizeof(float);
    cudaFuncSetAttribute(argmax_kernel,
                         cudaFuncAttributeMaxDynamicSharedMemorySize, smem_bytes);

    // 1) 0.5*||e||^2
    esq_kernel<<<KCODES / 256, 256>>>(emb);

    // 2) encoded_flat = transpose(z): per-b [256][1024] -> [1024][256]
    dim3 tb(32, 8);
    transpose_kernel<<<dim3(HW / 32, CDIM / 32, NB), tb>>>(z, enc, CDIM, HW);

    // 3) fused GEMM + argmax
    argmax_kernel<<<NPTS / BM, 256, smem_bytes>>>(enc, emb, idxf);

    // 4) gather / STE
    gather_kernel<<<NPTS * (CDIM / 4) / 256, 256>>>(enc, emb, qflat);

    // 5) quantized = transpose back: per-b [1024][256] -> [256][1024]
    transpose_kernel<<<dim3(CDIM / 32, HW / 32, NB), tb>>>(qflat, quant, HW, CDIM);
}

// round 5
// speedup vs baseline: 1.6302x; 1.6302x over previous
#include <cuda_runtime.h>
#include <cuda_bf16.h>
#include <math_constants.h>
#include <stdint.h>

// ---------------------------------------------------------------- constants
#define NB      16
#define CDIM    256
#define HW      1024
#define NPTS    16384
#define KCODES  8192

#define OFF_ENC   0
#define OFF_QF    (NPTS * CDIM)
#define OFF_IDX   (2 * NPTS * CDIM)
#define OFF_QUANT (2 * NPTS * CDIM + NPTS)

// split-bf16 K concat:  Xs = [xh | xl | xh],  Es = [eh | eh | el]
#define KSEG   768
#define ROWB   1536            // bytes per Xs/Es row (768 bf16)

// GEMM tiling
#define CTAM   128             // points per CTA
#define CTAN   256             // codes per n-tile
#define KBLK   32              // k elems per B stage
#define KB_PER_NT (KSEG / KBLK)          // 24
#define NTILES    (KCODES / CTAN)        // 32
#define TOTSTAGES (NTILES * KB_PER_NT)   // 768

#define A_SMEM_BYTES  (CTAM * ROWB)      // 196608
#define B_STAGE_BYTES (CTAN * KBLK * 2)  // 16384
#define SMEM_TOTAL    (A_SMEM_BYTES + 2 * B_STAGE_BYTES)  // 229376

__device__ int   g_idx[NPTS];
__device__ int   g_c1[NPTS];
__device__ int   g_c2[NPTS];
__device__ float g_half_esq[KCODES];
__device__ __align__(16) __nv_bfloat16 g_Xs[(size_t)NPTS * KSEG];   // 25.2 MB
__device__ __align__(16) __nv_bfloat16 g_Es[(size_t)KCODES * KSEG]; // 12.6 MB

// ---------------------------------------------------------------- helpers
__device__ __forceinline__ uint32_t smem_to_u32(const void* p) {
    uint32_t a;
    asm("{ .reg .u64 t; cvta.to.shared.u64 t, %1; cvt.u32.u64 %0, t; }" : "=r"(a) : "l"(p));
    return a;
}
__device__ __forceinline__ void cp_async16(uint32_t dst, const void* src) {
    asm volatile("cp.async.cg.shared.global [%0], [%1], 16;" :: "r"(dst), "l"(src));
}
#define CP_COMMIT() asm volatile("cp.async.commit_group;" ::: "memory")
#define CP_WAIT_0() asm volatile("cp.async.wait_group 0;" ::: "memory")

__device__ __forceinline__ void ldsm4(uint32_t* r, uint32_t addr) {
    asm volatile("ldmatrix.sync.aligned.m8n8.x4.shared.b16 {%0,%1,%2,%3}, [%4];"
                 : "=r"(r[0]), "=r"(r[1]), "=r"(r[2]), "=r"(r[3]) : "r"(addr));
}
__device__ __forceinline__ void mma16816(float* c, const uint32_t* a, const uint32_t* b) {
    asm volatile("mma.sync.aligned.m16n8k16.row.col.f32.bf16.bf16.f32 "
                 "{%0,%1,%2,%3}, {%4,%5,%6,%7}, {%8,%9}, {%0,%1,%2,%3};"
                 : "+f"(c[0]), "+f"(c[1]), "+f"(c[2]), "+f"(c[3])
                 : "r"(a[0]), "r"(a[1]), "r"(a[2]), "r"(a[3]),
                   "r"(b[0]), "r"(b[1]));
}

// bf16 hi/lo split of two floats, packed as bf16x2
__device__ __forceinline__ void pack2(float x, float y, uint32_t& h, uint32_t& l) {
    __nv_bfloat16 hx = __float2bfloat16(x), hy = __float2bfloat16(y);
    float rx = x - __bfloat162float(hx), ry = y - __bfloat162float(hy);
    __nv_bfloat16 lx = __float2bfloat16(rx), ly = __float2bfloat16(ry);
    h = (uint32_t)__bfloat16_as_ushort(hx) | ((uint32_t)__bfloat16_as_ushort(hy) << 16);
    l = (uint32_t)__bfloat16_as_ushort(lx) | ((uint32_t)__bfloat16_as_ushort(ly) << 16);
}

// ---------------------------------------------------------------- prep kernels
__global__ void esq_kernel(const float* __restrict__ E) {
    int k = blockIdx.x * blockDim.x + threadIdx.x;
    const float4* p = (const float4*)(E + (size_t)k * CDIM);
    float s = 0.f;
#pragma unroll
    for (int i = 0; i < CDIM / 4; ++i) {
        float4 v = p[i];
        s += v.x * v.x + v.y * v.y + v.z * v.z + v.w * v.w;
    }
    g_half_esq[k] = 0.5f * s;
}

// Xs row = [xh(256) | xl(256) | xh(256)]
__global__ void xconv_kernel(const float* __restrict__ X) {
    int t = blockIdx.x * blockDim.x + threadIdx.x;  // NPTS*32 threads
    int row = t >> 5, j = t & 31;                   // 8 elems per thread
    const float* p = X + (size_t)row * CDIM + j * 8;
    float4 a = *(const float4*)p;
    float4 b = *(const float4*)(p + 4);
    uint32_t h[4], l[4];
    pack2(a.x, a.y, h[0], l[0]); pack2(a.z, a.w, h[1], l[1]);
    pack2(b.x, b.y, h[2], l[2]); pack2(b.z, b.w, h[3], l[3]);
    uint32_t* base = (uint32_t*)g_Xs + (size_t)row * 384;
    *(uint4*)(base + j * 4)       = make_uint4(h[0], h[1], h[2], h[3]);
    *(uint4*)(base + 128 + j * 4) = make_uint4(l[0], l[1], l[2], l[3]);
    *(uint4*)(base + 256 + j * 4) = make_uint4(h[0], h[1], h[2], h[3]);
}

// Es row = [eh(256) | eh(256) | el(256)]
__global__ void econv_kernel(const float* __restrict__ E) {
    int t = blockIdx.x * blockDim.x + threadIdx.x;  // KCODES*32 threads
    int row = t >> 5, j = t & 31;
    const float* p = E + (size_t)row * CDIM + j * 8;
    float4 a = *(const float4*)p;
    float4 b = *(const float4*)(p + 4);
    uint32_t h[4], l[4];
    pack2(a.x, a.y, h[0], l[0]); pack2(a.z, a.w, h[1], l[1]);
    pack2(b.x, b.y, h[2], l[2]); pack2(b.z, b.w, h[3], l[3]);
    uint32_t* base = (uint32_t*)g_Es + (size_t)row * 384;
    *(uint4*)(base + j * 4)       = make_uint4(h[0], h[1], h[2], h[3]);
    *(uint4*)(base + 128 + j * 4) = make_uint4(h[0], h[1], h[2], h[3]);
    *(uint4*)(base + 256 + j * 4) = make_uint4(l[0], l[1], l[2], l[3]);
}

__global__ void transpose_kernel(const float* __restrict__ in,
                                 float* __restrict__ out, int R, int C) {
    __shared__ float tile[32][33];
    int b  = blockIdx.z;
    int c0 = blockIdx.x * 32;
    int r0 = blockIdx.y * 32;
    const float* pin = in  + (size_t)b * R * C;
    float*       pout = out + (size_t)b * R * C;
    int tx = threadIdx.x, ty = threadIdx.y;
#pragma unroll
    for (int i = 0; i < 32; i += 8)
        tile[ty + i][tx] = pin[(size_t)(r0 + ty + i) * C + c0 + tx];
    __syncthreads();
#pragma unroll
    for (int i = 0; i < 32; i += 8)
        pout[(size_t)(c0 + ty + i) * R + r0 + tx] = tile[tx][ty + i];
}

// ---------------------------------------------------------------- B stage loader
// stage s -> B slice [256 codes][32 k] at ntile=s/24, koff=(s%24)*32.
// SMEM row = 64B = 4 chunks of 16B, chunk swizzle c' = c ^ ((n>>1)&3).
__device__ __forceinline__ void load_B(uint32_t Bs, int s, int tid) {
    int ntile = s / KB_PER_NT;
    int kb = s - ntile * KB_PER_NT;
    const char* src = (const char*)g_Es + (size_t)(ntile * CTAN + tid) * ROWB + kb * 64;
    uint32_t dst = Bs + (uint32_t)(s & 1) * B_STAGE_BYTES + (uint32_t)tid * 64;
    int sw = (tid >> 1) & 3;
#pragma unroll
    for (int c = 0; c < 4; ++c)
        cp_async16(dst + (uint32_t)((c ^ sw) << 4), src + c * 16);
}

// ---------------------------------------------------------------- main kernel
// CTA: 128 points x all 8192 codes; 8 warps (2m x 4n) of 64x64; per-thread top-2.
__global__ __launch_bounds__(256, 1)
void argmax_mma_kernel() {
    extern __shared__ char smem[];
    uint32_t As = smem_to_u32(smem);
    uint32_t Bs = As + A_SMEM_BYTES;

    const int tid = threadIdx.x;
    const int wid = tid >> 5;
    const int L   = tid & 31;
    const int wm  = wid >> 2;         // 0..1
    const int wn  = wid & 3;          // 0..3
    const int m0  = blockIdx.x * CTAM;

    // ---- prologue: stage A tile (128 x 768 bf16), XOR-swizzled rows
    {
        int m = tid >> 1;
        int ch0 = (tid & 1) * 48;
        const char* srow = (const char*)g_Xs + (size_t)(m0 + m) * ROWB;
        uint32_t dbase = As + (uint32_t)m * ROWB;
#pragma unroll 8
        for (int t = 0; t < 48; ++t) {
            int c = ch0 + t;
            uint32_t swc = (uint32_t)((c & ~7) | ((c ^ m) & 7)) << 4;
            cp_async16(dbase + swc, srow + c * 16);
        }
    }
    load_B(Bs, 0, tid);
    CP_COMMIT();
    CP_WAIT_0();
    __syncthreads();

    // per-thread ldsm address components
    const int a_rowl = (L & 7) + ((L >> 3) & 1) * 8;      // row within 16
    const uint32_t a_base = As + (uint32_t)(wm * 64 + a_rowl) * ROWB;
    const int a_sw = L & 7;
    const int a_ch = (L >> 4) & 1;

    const int b_rowl = (L & 7) + ((L >> 4) & 1) * 8;
    const uint32_t b_roff = (uint32_t)(wn * 64 + b_rowl) * 64;
    const int b_sw = (b_rowl >> 1) & 3;
    const int b_ch = (L >> 3) & 1;

    float acc[4][8][4];
#pragma unroll
    for (int mt = 0; mt < 4; ++mt)
#pragma unroll
        for (int nt = 0; nt < 8; ++nt)
#pragma unroll
            for (int c = 0; c < 4; ++c) acc[mt][nt][c] = 0.f;

    float tb1[8], tb2[8];
    int   ti1[8], ti2[8];
#pragma unroll
    for (int r = 0; r < 8; ++r) {
        tb1[r] = -CUDART_INF_F; tb2[r] = -CUDART_INF_F;
        ti1[r] = 0x7FFFFFFF;    ti2[r] = 0x7FFFFFFF;
    }

    for (int s = 0; s < TOTSTAGES; ++s) {
        const int ntile = s / KB_PER_NT;
        const int smod  = s - ntile * KB_PER_NT;
        if (s + 1 < TOTSTAGES) { load_B(Bs, s + 1, tid); CP_COMMIT(); }

        const uint32_t bstage = Bs + (uint32_t)(s & 1) * B_STAGE_BYTES;
#pragma unroll
        for (int kk = 0; kk < 2; ++kk) {
            const int ksg = smod * 2 + kk;                 // 0..47
            // A fragments (4 m-tiles)
            uint32_t afr[4][4];
            {
                int c = ksg * 2 + a_ch;                    // 0..95
                uint32_t swc = (uint32_t)((c & ~7) | ((c ^ a_sw) & 7)) << 4;
#pragma unroll
                for (int mt = 0; mt < 4; ++mt)
                    ldsm4(afr[mt], a_base + (uint32_t)(mt * 16) * ROWB + swc);
            }
            // B fragments (4 x n16)
            uint32_t bfr[4][4];
            {
                int c = kk * 2 + b_ch;                     // 0..3
                uint32_t swc = (uint32_t)((c ^ b_sw) << 4);
#pragma unroll
                for (int nt2 = 0; nt2 < 4; ++nt2)
                    ldsm4(bfr[nt2], bstage + b_roff + (uint32_t)(nt2 * 16) * 64 + swc);
            }
#pragma unroll
            for (int mt = 0; mt < 4; ++mt)
#pragma unroll
                for (int nt = 0; nt < 8; ++nt)
                    mma16816(acc[mt][nt], afr[mt], &bfr[nt >> 1][(nt & 1) * 2]);
        }

        // end of n-tile: fold acc into per-thread running top-2, reset acc
        if (smod == KB_PER_NT - 1) {
            const int nb = ntile * CTAN + wn * 64 + (L & 3) * 2;
#pragma unroll
            for (int mt = 0; mt < 4; ++mt)
#pragma unroll
                for (int hf = 0; hf < 2; ++hf) {
                    const int rr = mt * 2 + hf;
                    float v1 = tb1[rr], v2 = tb2[rr];
                    int   j1 = ti1[rr], j2 = ti2[rr];
#pragma unroll
                    for (int nt = 0; nt < 8; ++nt)
#pragma unroll
                        for (int cc = 0; cc < 2; ++cc) {
                            const int k = nb + nt * 8 + cc;
                            float sc = acc[mt][nt][hf * 2 + cc] - __ldg(&g_half_esq[k]);
                            acc[mt][nt][hf * 2 + cc] = 0.f;
                            if (sc > v1 || (sc == v1 && k < j1)) {
                                v2 = v1; j2 = j1; v1 = sc; j1 = k;
                            } else if (sc > v2 || (sc == v2 && k < j2)) {
                                v2 = sc; j2 = k;
                            }
                        }
                    tb1[rr] = v1; tb2[rr] = v2; ti1[rr] = j1; ti2[rr] = j2;
                }
        }

        if (s + 1 < TOTSTAGES) CP_WAIT_0();
        __syncthreads();
    }

    // ---- final cross-thread top-2 reduction (reuse B smem area: 32 KB)
    float* rs = (float*)(smem + A_SMEM_BYTES);
    int*   ri = (int*)(smem + A_SMEM_BYTES + CTAM * 16 * 2 * 4);
    const int slot = wn * 4 + (L & 3);
#pragma unroll
    for (int mt = 0; mt < 4; ++mt)
#pragma unroll
        for (int hf = 0; hf < 2; ++hf) {
            const int row = wm * 64 + mt * 16 + (L >> 2) + hf * 8;
            const int rr = mt * 2 + hf;
            rs[(row * 16 + slot) * 2 + 0] = tb1[rr];
            rs[(row * 16 + slot) * 2 + 1] = tb2[rr];
            ri[(row * 16 + slot) * 2 + 0] = ti1[rr];
            ri[(row * 16 + slot) * 2 + 1] = ti2[rr];
        }
    __syncthreads();
    if (tid < CTAM) {
        float v1 = -CUDART_INF_F, v2 = -CUDART_INF_F;
        int j1 = 0x7FFFFFFF, j2 = 0x7FFFFFFF;
#pragma unroll 4
        for (int e = 0; e < 32; ++e) {
            float sc = rs[tid * 32 + e];
            int   k  = ri[tid * 32 + e];
            if (sc > v1 || (sc == v1 && k < j1)) {
                v2 = v1; j2 = j1; v1 = sc; j1 = k;
            } else if ((sc > v2 || (sc == v2 && k < j2)) && k != j1) {
                v2 = sc; j2 = k;
            }
        }
        g_c1[m0 + tid] = j1;
        g_c2[m0 + tid] = j2;
    }
}

// ---------------------------------------------------------------- exact rescore
__global__ void rescore_kernel(const float* __restrict__ X,
                               const float* __restrict__ E,
                               float* __restrict__ idxf) {
    int w = (blockIdx.x * blockDim.x + threadIdx.x) >> 5;
    int lane = threadIdx.x & 31;
    int c1 = g_c1[w], c2 = g_c2[w];
    const float4* x  = (const float4*)(X + (size_t)w  * CDIM) + lane * 2;
    const float4* e1 = (const float4*)(E + (size_t)c1 * CDIM) + lane * 2;
    const float4* e2 = (const float4*)(E + (size_t)c2 * CDIM) + lane * 2;
    float s1 = 0.f, s2 = 0.f;
#pragma unroll
    for (int r = 0; r < 2; ++r) {
        float4 xx = x[r], a = e1[r], b = e2[r];
        s1 += xx.x * a.x + xx.y * a.y + xx.z * a.z + xx.w * a.w;
        s2 += xx.x * b.x + xx.y * b.y + xx.z * b.z + xx.w * b.w;
    }
#pragma unroll
    for (int o = 16; o > 0; o >>= 1) {
        s1 += __shfl_xor_sync(0xFFFFFFFF, s1, o);
        s2 += __shfl_xor_sync(0xFFFFFFFF, s2, o);
    }
    if (lane == 0) {
        float sc1 = s1 - g_half_esq[c1];
        float sc2 = s2 - g_half_esq[c2];
        int best = (sc2 > sc1 || (sc2 == sc1 && c2 < c1)) ? c2 : c1;
        g_idx[w] = best;
        idxf[w] = (float)best;
    }
}

// ---------------------------------------------------------------- gather / STE
__global__ void gather_kernel(const float* __restrict__ enc,
                              const float* __restrict__ E,
                              float* __restrict__ qflat) {
    int t = blockIdx.x * blockDim.x + threadIdx.x;
    int n = t >> 6;
    int j = t & 63;
    int idx = g_idx[n];
    float4 x = *(const float4*)(enc + (size_t)n * CDIM + j * 4);
    float4 e = *(const float4*)(E + (size_t)idx * CDIM + j * 4);
    float4 q;
    q.x = x.x + (e.x - x.x);
    q.y = x.y + (e.y - x.y);
    q.z = x.z + (e.z - x.z);
    q.w = x.w + (e.w - x.w);
    *(float4*)(qflat + (size_t)n * CDIM + j * 4) = q;
}

// ---------------------------------------------------------------- launch
extern "C" void kernel_launch(void* const* d_in, const int* in_sizes, int n_in,
                              void* d_out, int out_size) {
    const float* z   = (const float*)d_in[0];   // (16, 256, 32, 32)
    const float* emb = (const float*)d_in[1];   // (8192, 256)
    float* out   = (float*)d_out;
    float* enc   = out + OFF_ENC;
    float* qflat = out + OFF_QF;
    float* idxf  = out + OFF_IDX;
    float* quant = out + OFF_QUANT;

    cudaFuncSetAttribute(argmax_mma_kernel,
                         cudaFuncAttributeMaxDynamicSharedMemorySize, SMEM_TOTAL);

    esq_kernel<<<KCODES / 256, 256>>>(emb);
    econv_kernel<<<KCODES * 32 / 256, 256>>>(emb);

    dim3 tb32(32, 8);
    transpose_kernel<<<dim3(HW / 32, CDIM / 32, NB), tb32>>>(z, enc, CDIM, HW);
    xconv_kernel<<<NPTS * 32 / 256, 256>>>(enc);

    argmax_mma_kernel<<<NPTS / CTAM, 256, SMEM_TOTAL>>>();

    rescore_kernel<<<NPTS * 32 / 256, 256>>>(enc, emb, idxf);
    gather_kernel<<<NPTS * (CDIM / 4) / 256, 256>>>(enc, emb, qflat);
    transpose_kernel<<<dim3(CDIM / 32, HW / 32, NB), tb32>>>(qflat, quant, HW, CDIM);
}

// round 6
// speedup vs baseline: 3.8949x; 2.3892x over previous
#include <cuda_runtime.h>
#include <cuda_bf16.h>
#include <math_constants.h>
#include <stdint.h>

// ---------------------------------------------------------------- constants
#define NB      16
#define CDIM    256
#define HW      1024
#define NPTS    16384
#define KCODES  8192

#define OFF_ENC   0
#define OFF_QF    (NPTS * CDIM)
#define OFF_IDX   (2 * NPTS * CDIM)
#define OFF_QUANT (2 * NPTS * CDIM + NPTS)

// GEMM tiling: single-pass bf16, K = 256
#define ROWB   512              // bytes per bf16 row (256 * 2)
#define CTAM   128              // points per CTA
#define CTAN   128              // codes per n-tile
#define KBLK   64               // k elems per B stage (128 B per code row)
#define KB_PER_NT 4             // 256 / 64
#define NTILES    (KCODES / CTAN)          // 64
#define TOTST     (NTILES * KB_PER_NT)     // 256

#define A_SMEM_BYTES  (CTAM * ROWB)        // 65536
#define B_STAGE_BYTES (CTAN * KBLK * 2)    // 16384
#define SMEM_TOTAL    (A_SMEM_BYTES + 2 * B_STAGE_BYTES)  // 98304

__device__ int   g_idx[NPTS];
__device__ int4  g_c4[NPTS];
__device__ float g_half_esq[KCODES];
__device__ __align__(16) __nv_bfloat16 g_Xb[(size_t)NPTS * CDIM];   // 8 MB
__device__ __align__(16) __nv_bfloat16 g_Eb[(size_t)KCODES * CDIM]; // 4 MB

// ---------------------------------------------------------------- helpers
__device__ __forceinline__ uint32_t smem_to_u32(const void* p) {
    uint32_t a;
    asm("{ .reg .u64 t; cvta.to.shared.u64 t, %1; cvt.u32.u64 %0, t; }" : "=r"(a) : "l"(p));
    return a;
}
__device__ __forceinline__ void cp_async16(uint32_t dst, const void* src) {
    asm volatile("cp.async.cg.shared.global [%0], [%1], 16;" :: "r"(dst), "l"(src));
}
#define CP_COMMIT() asm volatile("cp.async.commit_group;" ::: "memory")
#define CP_WAIT_0() asm volatile("cp.async.wait_group 0;" ::: "memory")

__device__ __forceinline__ void ldsm4(uint32_t* r, uint32_t addr) {
    asm volatile("ldmatrix.sync.aligned.m8n8.x4.shared.b16 {%0,%1,%2,%3}, [%4];"
                 : "=r"(r[0]), "=r"(r[1]), "=r"(r[2]), "=r"(r[3]) : "r"(addr));
}
__device__ __forceinline__ void mma16816(float* c, const uint32_t* a, const uint32_t* b) {
    asm volatile("mma.sync.aligned.m16n8k16.row.col.f32.bf16.bf16.f32 "
                 "{%0,%1,%2,%3}, {%4,%5,%6,%7}, {%8,%9}, {%0,%1,%2,%3};"
                 : "+f"(c[0]), "+f"(c[1]), "+f"(c[2]), "+f"(c[3])
                 : "r"(a[0]), "r"(a[1]), "r"(a[2]), "r"(a[3]),
                   "r"(b[0]), "r"(b[1]));
}
__device__ __forceinline__ uint32_t packbf(float x, float y) {
    __nv_bfloat16 hx = __float2bfloat16(x), hy = __float2bfloat16(y);
    return (uint32_t)__bfloat16_as_ushort(hx) | ((uint32_t)__bfloat16_as_ushort(hy) << 16);
}

// ---------------------------------------------------------------- prep kernels
// E -> bf16 row + half ||e||^2 (one warp per code row)
__global__ void prep_e_kernel(const float* __restrict__ E) {
    int t = blockIdx.x * blockDim.x + threadIdx.x;  // KCODES*32 threads
    int row = t >> 5, j = t & 31;                   // 8 elems per thread
    const float* p = E + (size_t)row * CDIM + j * 8;
    float4 a = *(const float4*)p;
    float4 b = *(const float4*)(p + 4);
    uint4 w;
    w.x = packbf(a.x, a.y); w.y = packbf(a.z, a.w);
    w.z = packbf(b.x, b.y); w.w = packbf(b.z, b.w);
    *(uint4*)((uint32_t*)g_Eb + (size_t)row * 128 + j * 4) = w;
    float s = a.x * a.x + a.y * a.y + a.z * a.z + a.w * a.w
            + b.x * b.x + b.y * b.y + b.z * b.z + b.w * b.w;
#pragma unroll
    for (int o = 16; o > 0; o >>= 1) s += __shfl_xor_sync(0xFFFFFFFF, s, o);
    if (j == 0) g_half_esq[row] = 0.5f * s;
}

// z (b,c,h,w) -> enc fp32 (N, c) and Xb bf16 (N, c)
__global__ void transpose_enc_kernel(const float* __restrict__ in,
                                     float* __restrict__ out,
                                     __nv_bfloat16* __restrict__ outb) {
    __shared__ float tile[32][33];
    int b  = blockIdx.z;
    int c0 = blockIdx.x * 32;   // over HW
    int r0 = blockIdx.y * 32;   // over CDIM
    const float* pin = in + (size_t)b * CDIM * HW;
    float* pout = out + (size_t)b * CDIM * HW;
    __nv_bfloat16* poutb = outb + (size_t)b * CDIM * HW;
    int tx = threadIdx.x, ty = threadIdx.y;
#pragma unroll
    for (int i = 0; i < 32; i += 8)
        tile[ty + i][tx] = pin[(size_t)(r0 + ty + i) * HW + c0 + tx];
    __syncthreads();
#pragma unroll
    for (int i = 0; i < 32; i += 8) {
        float v = tile[tx][ty + i];
        size_t o = (size_t)(c0 + ty + i) * CDIM + r0 + tx;
        pout[o] = v;
        poutb[o] = __float2bfloat16(v);
    }
}

__global__ void transpose_kernel(const float* __restrict__ in,
                                 float* __restrict__ out, int R, int C) {
    __shared__ float tile[32][33];
    int b  = blockIdx.z;
    int c0 = blockIdx.x * 32;
    int r0 = blockIdx.y * 32;
    const float* pin = in  + (size_t)b * R * C;
    float*       pout = out + (size_t)b * R * C;
    int tx = threadIdx.x, ty = threadIdx.y;
#pragma unroll
    for (int i = 0; i < 32; i += 8)
        tile[ty + i][tx] = pin[(size_t)(r0 + ty + i) * C + c0 + tx];
    __syncthreads();
#pragma unroll
    for (int i = 0; i < 32; i += 8)
        pout[(size_t)(c0 + ty + i) * R + r0 + tx] = tile[tx][ty + i];
}

// ---------------------------------------------------------------- B stage loader
// stage s -> [128 codes][64 k] slice; SMEM row = 128B = 8 chunks of 16B,
// chunk swizzle c' = c ^ (row & 7)  (row stride = one full bank phase).
__device__ __forceinline__ void load_B(uint32_t Bs, int s, int tid) {
    const int ntile = s >> 2;
    const int kb = s & 3;
    const int r = tid >> 1;
    const int cb = (tid & 1) * 4;
    const char* src = (const char*)g_Eb + (size_t)(ntile * CTAN + r) * ROWB + kb * 128;
    uint32_t dst = Bs + (uint32_t)(s & 1) * B_STAGE_BYTES + (uint32_t)r * 128;
    const int sw = r & 7;
#pragma unroll
    for (int q = 0; q < 4; ++q) {
        int c = cb + q;
        cp_async16(dst + (uint32_t)((c ^ sw) << 4), src + c * 16);
    }
}

// ---------------------------------------------------------------- main kernel
// CTA: 128 points x all 8192 codes, single-pass bf16, per-thread top-2,
// per-row top-4 candidates. 8 warps (2m x 4n), warp tile 64x32.
__global__ __launch_bounds__(256, 1)
void argmax_mma_kernel() {
    extern __shared__ char smem[];
    uint32_t As = smem_to_u32(smem);
    uint32_t Bs = As + A_SMEM_BYTES;

    const int tid = threadIdx.x;
    const int wid = tid >> 5;
    const int L   = tid & 31;
    const int wm  = wid >> 2;         // 0..1
    const int wn  = wid & 3;          // 0..3
    const int m0  = blockIdx.x * CTAM;

    // ---- stage A (128 x 256 bf16), 32 chunks/row, XOR swizzle on low 3 bits
    {
        const int m = tid >> 1;
        const int ch0 = (tid & 1) * 16;
        const char* srow = (const char*)g_Xb + (size_t)(m0 + m) * ROWB;
        uint32_t dbase = As + (uint32_t)m * ROWB;
#pragma unroll
        for (int t = 0; t < 16; ++t) {
            int c = ch0 + t;
            uint32_t swc = (uint32_t)((c & ~7) | ((c ^ m) & 7)) << 4;
            cp_async16(dbase + swc, srow + c * 16);
        }
    }
    load_B(Bs, 0, tid);
    CP_COMMIT();
    CP_WAIT_0();
    __syncthreads();

    // ldsm address components (validated fragment mapping from R5)
    const int a_rowl = (L & 7) + ((L >> 3) & 1) * 8;
    const uint32_t a_base = As + (uint32_t)(wm * 64 + a_rowl) * ROWB;
    const int a_sw = L & 7;
    const int a_ch = (L >> 4) & 1;

    const int b_rowl = (L & 7) + ((L >> 4) & 1) * 8;
    const int b_ch = (L >> 3) & 1;
    const int b_sw = b_rowl & 7;
    const uint32_t b_roff = (uint32_t)(wn * 32 + b_rowl) * 128;

    float acc[4][4][4];
#pragma unroll
    for (int mt = 0; mt < 4; ++mt)
#pragma unroll
        for (int nt = 0; nt < 4; ++nt)
#pragma unroll
            for (int c = 0; c < 4; ++c) acc[mt][nt][c] = 0.f;

    float tb1[8], tb2[8];
    int   ti1[8], ti2[8];
#pragma unroll
    for (int r = 0; r < 8; ++r) {
        tb1[r] = -CUDART_INF_F; tb2[r] = -CUDART_INF_F;
        ti1[r] = 0x7FFFFFFF;    ti2[r] = 0x7FFFFFFF;
    }

    for (int s = 0; s < TOTST; ++s) {
        const int ntile = s >> 2;
        const int kb = s & 3;
        if (s + 1 < TOTST) { load_B(Bs, s + 1, tid); CP_COMMIT(); }

        const uint32_t bstage = Bs + (uint32_t)(s & 1) * B_STAGE_BYTES;
#pragma unroll
        for (int kk = 0; kk < 4; ++kk) {
            uint32_t afr[4][4];
            {
                int c = (kb * 4 + kk) * 2 + a_ch;               // 0..31
                uint32_t swc = (uint32_t)((c & ~7) | ((c ^ a_sw) & 7)) << 4;
#pragma unroll
                for (int mt = 0; mt < 4; ++mt)
                    ldsm4(afr[mt], a_base + (uint32_t)(mt * 16) * ROWB + swc);
            }
            uint32_t bfr[2][4];
            {
                int c = kk * 2 + b_ch;                          // 0..7
                uint32_t swc = (uint32_t)((c ^ b_sw) << 4);
#pragma unroll
                for (int nt2 = 0; nt2 < 2; ++nt2)
                    ldsm4(bfr[nt2], bstage + b_roff + (uint32_t)(nt2 * 16) * 128 + swc);
            }
#pragma unroll
            for (int mt = 0; mt < 4; ++mt)
#pragma unroll
                for (int nt = 0; nt < 4; ++nt)
                    mma16816(acc[mt][nt], afr[mt], &bfr[nt >> 1][(nt & 1) * 2]);
        }

        // end of n-tile: fold into per-thread top-2, reset acc
        if (kb == 3) {
            const int nb = ntile * CTAN + wn * 32 + (L & 3) * 2;
            float h[4][2];
#pragma unroll
            for (int nt = 0; nt < 4; ++nt) {
                h[nt][0] = g_half_esq[nb + nt * 8];
                h[nt][1] = g_half_esq[nb + nt * 8 + 1];
            }
#pragma unroll
            for (int mt = 0; mt < 4; ++mt)
#pragma unroll
                for (int hf = 0; hf < 2; ++hf) {
                    const int rr = mt * 2 + hf;
                    float v1 = tb1[rr], v2 = tb2[rr];
                    int   j1 = ti1[rr], j2 = ti2[rr];
#pragma unroll
                    for (int nt = 0; nt < 4; ++nt)
#pragma unroll
                        for (int cc = 0; cc < 2; ++cc) {
                            const int k = nb + nt * 8 + cc;
                            float sc = acc[mt][nt][hf * 2 + cc] - h[nt][cc];
                            acc[mt][nt][hf * 2 + cc] = 0.f;
                            if (sc > v1 || (sc == v1 && k < j1)) {
                                v2 = v1; j2 = j1; v1 = sc; j1 = k;
                            } else if (sc > v2 || (sc == v2 && k < j2)) {
                                v2 = sc; j2 = k;
                            }
                        }
                    tb1[rr] = v1; tb2[rr] = v2; ti1[rr] = j1; ti2[rr] = j2;
                }
        }

        if (s + 1 < TOTST) CP_WAIT_0();
        __syncthreads();
    }

    // ---- final per-row top-4 from 16 slots x top-2 (reuse B smem: 32 KB)
    float* rs = (float*)(smem + A_SMEM_BYTES);
    int*   ri = (int*)(smem + A_SMEM_BYTES + CTAM * 16 * 2 * 4);
    const int slot = wn * 4 + (L & 3);
#pragma unroll
    for (int mt = 0; mt < 4; ++mt)
#pragma unroll
        for (int hf = 0; hf < 2; ++hf) {
            const int row = wm * 64 + mt * 16 + (L >> 2) + hf * 8;
            const int rr = mt * 2 + hf;
            rs[(row * 16 + slot) * 2 + 0] = tb1[rr];
            rs[(row * 16 + slot) * 2 + 1] = tb2[rr];
            ri[(row * 16 + slot) * 2 + 0] = ti1[rr];
            ri[(row * 16 + slot) * 2 + 1] = ti2[rr];
        }
    __syncthreads();
    if (tid < CTAM) {
        float v[4] = {-CUDART_INF_F, -CUDART_INF_F, -CUDART_INF_F, -CUDART_INF_F};
        int   id[4] = {0x7FFFFFFF, 0x7FFFFFFF, 0x7FFFFFFF, 0x7FFFFFFF};
#pragma unroll 4
        for (int e = 0; e < 32; ++e) {
            float sc = rs[tid * 32 + e];
            int   k  = ri[tid * 32 + e];
            // 4-entry insertion (score desc, idx asc)
            if (sc > v[3] || (sc == v[3] && k < id[3])) {
                int p = 3;
                while (p > 0 && (sc > v[p - 1] || (sc == v[p - 1] && k < id[p - 1]))) {
                    v[p] = v[p - 1]; id[p] = id[p - 1]; --p;
                }
                v[p] = sc; id[p] = k;
            }
        }
        g_c4[m0 + tid] = make_int4(id[0], id[1], id[2], id[3]);
    }
}

// ---------------------------------------------------------------- exact rescore (4 cands)
__global__ void rescore_kernel(const float* __restrict__ X,
                               const float* __restrict__ E,
                               float* __restrict__ idxf) {
    int w = (blockIdx.x * blockDim.x + threadIdx.x) >> 5;
    int lane = threadIdx.x & 31;
    int4 c = g_c4[w];
    int ks[4] = {c.x, c.y, c.z, c.w};
    const float4* x = (const float4*)(X + (size_t)w * CDIM) + lane * 2;
    float4 x0 = x[0], x1 = x[1];
    float s[4];
#pragma unroll
    for (int i = 0; i < 4; ++i) {
        const float4* e = (const float4*)(E + (size_t)ks[i] * CDIM) + lane * 2;
        float4 a = e[0], b = e[1];
        s[i] = x0.x * a.x + x0.y * a.y + x0.z * a.z + x0.w * a.w
             + x1.x * b.x + x1.y * b.y + x1.z * b.z + x1.w * b.w;
    }
#pragma unroll
    for (int o = 16; o > 0; o >>= 1)
#pragma unroll
        for (int i = 0; i < 4; ++i)
            s[i] += __shfl_xor_sync(0xFFFFFFFF, s[i], o);
    if (lane == 0) {
        float bv = s[0] - g_half_esq[ks[0]];
        int bk = ks[0];
#pragma unroll
        for (int i = 1; i < 4; ++i) {
            float sc = s[i] - g_half_esq[ks[i]];
            if (sc > bv || (sc == bv && ks[i] < bk)) { bv = sc; bk = ks[i]; }
        }
        g_idx[w] = bk;
        idxf[w] = (float)bk;
    }
}

// ---------------------------------------------------------------- gather / STE
__global__ void gather_kernel(const float* __restrict__ enc,
                              const float* __restrict__ E,
                              float* __restrict__ qflat) {
    int t = blockIdx.x * blockDim.x + threadIdx.x;
    int n = t >> 6;
    int j = t & 63;
    int idx = g_idx[n];
    float4 x = *(const float4*)(enc + (size_t)n * CDIM + j * 4);
    float4 e = *(const float4*)(E + (size_t)idx * CDIM + j * 4);
    float4 q;
    q.x = x.x + (e.x - x.x);
    q.y = x.y + (e.y - x.y);
    q.z = x.z + (e.z - x.z);
    q.w = x.w + (e.w - x.w);
    *(float4*)(qflat + (size_t)n * CDIM + j * 4) = q;
}

// ---------------------------------------------------------------- launch
extern "C" void kernel_launch(void* const* d_in, const int* in_sizes, int n_in,
                              void* d_out, int out_size) {
    const float* z   = (const float*)d_in[0];   // (16, 256, 32, 32)
    const float* emb = (const float*)d_in[1];   // (8192, 256)
    float* out   = (float*)d_out;
    float* enc   = out + OFF_ENC;
    float* qflat = out + OFF_QF;
    float* idxf  = out + OFF_IDX;
    float* quant = out + OFF_QUANT;

    cudaFuncSetAttribute(argmax_mma_kernel,
                         cudaFuncAttributeMaxDynamicSharedMemorySize, SMEM_TOTAL);

    prep_e_kernel<<<KCODES * 32 / 256, 256>>>(emb);

    dim3 tb32(32, 8);
    __nv_bfloat16* xb;
    cudaGetSymbolAddress((void**)&xb, g_Xb);
    transpose_enc_kernel<<<dim3(HW / 32, CDIM / 32, NB), tb32>>>(z, enc, xb);

    argmax_mma_kernel<<<NPTS / CTAM, 256, SMEM_TOTAL>>>();

    rescore_kernel<<<NPTS * 32 / 256, 256>>>(enc, emb, idxf);
    gather_kernel<<<NPTS * (CDIM / 4) / 256, 256>>>(enc, emb, qflat);
    transpose_kernel<<<dim3(CDIM / 32, HW / 32, NB), tb32>>>(qflat, quant, HW, CDIM);
}

// round 8
// speedup vs baseline: 5.2333x; 1.3436x over previous
#include <cuda_runtime.h>
#include <cuda_bf16.h>
#include <math_constants.h>
#include <stdint.h>

// ---------------------------------------------------------------- constants
#define NB      16
#define CDIM    256
#define HW      1024
#define NPTS    16384
#define KCODES  8192

#define OFF_ENC   0
#define OFF_QF    (NPTS * CDIM)
#define OFF_IDX   (2 * NPTS * CDIM)
#define OFF_QUANT (2 * NPTS * CDIM + NPTS)

// int8 GEMM tiling
#define ROWB   256               // bytes per int8 row (256 k)
#define CTAM   128               // points per CTA
#define CTAN   128               // codes per stage (= n-tile)
#define NSTAGE (KCODES / CTAN)   // 64

#define A_BYTES  (CTAM * ROWB)           // 32768
#define B_STAGE  (CTAN * ROWB)           // 32768
#define SMEM_TOTAL (A_BYTES + 2 * B_STAGE)  // 98304

__device__ int    g_idx[NPTS];
__device__ int4   g_c8a[NPTS];
__device__ int4   g_c8b[NPTS];
__device__ float  g_sx[NPTS];
__device__ float2 g_seh[KCODES];   // (se scale, 0.5*||e||^2 exact fp32)
__device__ __align__(16) int8_t g_Xq[(size_t)NPTS * CDIM];
__device__ __align__(16) int8_t g_Eq[(size_t)KCODES * CDIM];

// ---------------------------------------------------------------- helpers
__device__ __forceinline__ uint32_t smem_to_u32(const void* p) {
    uint32_t a;
    asm("{ .reg .u64 t; cvta.to.shared.u64 t, %1; cvt.u32.u64 %0, t; }" : "=r"(a) : "l"(p));
    return a;
}
__device__ __forceinline__ void cp_async16(uint32_t dst, const void* src) {
    asm volatile("cp.async.cg.shared.global [%0], [%1], 16;" :: "r"(dst), "l"(src));
}
#define CP_COMMIT() asm volatile("cp.async.commit_group;" ::: "memory")
#define CP_WAIT_0() asm volatile("cp.async.wait_group 0;" ::: "memory")

__device__ __forceinline__ void ldsm4(uint32_t* r, uint32_t addr) {
    asm volatile("ldmatrix.sync.aligned.m8n8.x4.shared.b16 {%0,%1,%2,%3}, [%4];"
                 : "=r"(r[0]), "=r"(r[1]), "=r"(r[2]), "=r"(r[3]) : "r"(addr));
}
__device__ __forceinline__ void imma16832(int* c, const uint32_t* a, const uint32_t* b) {
    asm volatile("mma.sync.aligned.m16n8k32.row.col.s32.s8.s8.s32 "
                 "{%0,%1,%2,%3}, {%4,%5,%6,%7}, {%8,%9}, {%0,%1,%2,%3};"
                 : "+r"(c[0]), "+r"(c[1]), "+r"(c[2]), "+r"(c[3])
                 : "r"(a[0]), "r"(a[1]), "r"(a[2]), "r"(a[3]),
                   "r"(b[0]), "r"(b[1]));
}
__device__ __forceinline__ uint32_t pack4(int a, int b, int c, int d) {
    return (uint32_t)(a & 255) | ((uint32_t)(b & 255) << 8)
         | ((uint32_t)(c & 255) << 16) | ((uint32_t)(d & 255) << 24);
}

// ---------------------------------------------------------------- prep kernels
// E row -> int8 quant + (se, 0.5||e||^2); one warp per code row
__global__ void prep_e_kernel(const float* __restrict__ E) {
    int t = blockIdx.x * blockDim.x + threadIdx.x;
    int row = t >> 5, j = t & 31;                   // 8 elems per thread
    const float* p = E + (size_t)row * CDIM + j * 8;
    float4 a = *(const float4*)p;
    float4 b = *(const float4*)(p + 4);
    float v[8] = {a.x, a.y, a.z, a.w, b.x, b.y, b.z, b.w};
    float mx = 0.f, ss = 0.f;
#pragma unroll
    for (int i = 0; i < 8; ++i) { mx = fmaxf(mx, fabsf(v[i])); ss += v[i] * v[i]; }
#pragma unroll
    for (int o = 16; o > 0; o >>= 1) {
        mx = fmaxf(mx, __shfl_xor_sync(0xFFFFFFFF, mx, o));
        ss += __shfl_xor_sync(0xFFFFFFFF, ss, o);
    }
    float inv = (mx > 0.f) ? 127.f / mx : 0.f;
    int q[8];
#pragma unroll
    for (int i = 0; i < 8; ++i) q[i] = __float2int_rn(v[i] * inv);
    uint2 w;
    w.x = pack4(q[0], q[1], q[2], q[3]);
    w.y = pack4(q[4], q[5], q[6], q[7]);
    *(uint2*)(g_Eq + (size_t)row * CDIM + j * 8) = w;
    if (j == 0) g_seh[row] = make_float2(mx * (1.f / 127.f), 0.5f * ss);
}

// X row (enc fp32) -> int8 quant + sx; one warp per point row
__global__ void prep_x_kernel(const float* __restrict__ X) {
    int t = blockIdx.x * blockDim.x + threadIdx.x;
    int row = t >> 5, j = t & 31;
    const float* p = X + (size_t)row * CDIM + j * 8;
    float4 a = *(const float4*)p;
    float4 b = *(const float4*)(p + 4);
    float v[8] = {a.x, a.y, a.z, a.w, b.x, b.y, b.z, b.w};
    float mx = 0.f;
#pragma unroll
    for (int i = 0; i < 8; ++i) mx = fmaxf(mx, fabsf(v[i]));
#pragma unroll
    for (int o = 16; o > 0; o >>= 1)
        mx = fmaxf(mx, __shfl_xor_sync(0xFFFFFFFF, mx, o));
    float inv = (mx > 0.f) ? 127.f / mx : 0.f;
    int q[8];
#pragma unroll
    for (int i = 0; i < 8; ++i) q[i] = __float2int_rn(v[i] * inv);
    uint2 w;
    w.x = pack4(q[0], q[1], q[2], q[3]);
    w.y = pack4(q[4], q[5], q[6], q[7]);
    *(uint2*)(g_Xq + (size_t)row * CDIM + j * 8) = w;
    if (j == 0) g_sx[row] = mx * (1.f / 127.f);
}

// z (b,c,h,w) -> enc fp32 (N, c)
__global__ void transpose_kernel(const float* __restrict__ in,
                                 float* __restrict__ out, int R, int C) {
    __shared__ float tile[32][33];
    int b  = blockIdx.z;
    int c0 = blockIdx.x * 32;
    int r0 = blockIdx.y * 32;
    const float* pin = in  + (size_t)b * R * C;
    float*       pout = out + (size_t)b * R * C;
    int tx = threadIdx.x, ty = threadIdx.y;
#pragma unroll
    for (int i = 0; i < 32; i += 8)
        tile[ty + i][tx] = pin[(size_t)(r0 + ty + i) * C + c0 + tx];
    __syncthreads();
#pragma unroll
    for (int i = 0; i < 32; i += 8)
        pout[(size_t)(c0 + ty + i) * R + r0 + tx] = tile[tx][ty + i];
}

// ---------------------------------------------------------------- stage loader
// 128 rows x 256 B; 16 chunks of 16B per row, chunk swizzle c' = (c&~7)|((c^r)&7)
__device__ __forceinline__ void load_B(uint32_t Bs, int s, int tid) {
    const int r = tid >> 1;
    const int c0 = (tid & 1) * 8;
    const char* src = (const char*)g_Eq + (size_t)(s * CTAN + r) * ROWB;
    uint32_t dst = Bs + (uint32_t)(s & 1) * B_STAGE + (uint32_t)r * ROWB;
#pragma unroll
    for (int q = 0; q < 8; ++q) {
        int c = c0 + q;
        cp_async16(dst + (uint32_t)(((c & ~7) | ((c ^ r) & 7)) << 4), src + c * 16);
    }
}

// ---------------------------------------------------------------- main kernel
// CTA: 128 points x 8192 codes, int8 IMMA k32; per-thread-row top-3 -> row top-8.
__global__ __launch_bounds__(256, 1)
void argmax_imma_kernel() {
    extern __shared__ char smem[];
    uint32_t As = smem_to_u32(smem);
    uint32_t Bs = As + A_BYTES;

    const int tid = threadIdx.x;
    const int wid = tid >> 5;
    const int L   = tid & 31;
    const int wm  = wid >> 2;         // 0..1
    const int wn  = wid & 3;          // 0..3
    const int m0  = blockIdx.x * CTAM;

    // ---- stage A (128 x 256 int8), same swizzle as B
    {
        const int r = tid >> 1;
        const int c0 = (tid & 1) * 8;
        const char* src = (const char*)g_Xq + (size_t)(m0 + r) * ROWB;
        uint32_t dst = As + (uint32_t)r * ROWB;
#pragma unroll
        for (int q = 0; q < 8; ++q) {
            int c = c0 + q;
            cp_async16(dst + (uint32_t)(((c & ~7) | ((c ^ r) & 7)) << 4), src + c * 16);
        }
    }
    load_B(Bs, 0, tid);
    CP_COMMIT();
    CP_WAIT_0();
    __syncthreads();

    // ldsm address components (byte-identical recipe to validated R6 mapping)
    const int a_rowl = (L & 7) + ((L >> 3) & 1) * 8;
    const uint32_t a_base = As + (uint32_t)(wm * 64 + a_rowl) * ROWB;
    const int a_sw = L & 7;
    const int a_ch = (L >> 4) & 1;          // 16B half within 32B k-step

    const int b_rowl = (L & 7) + ((L >> 4) & 1) * 8;
    const int b_ch = (L >> 3) & 1;
    const int b_sw = L & 7;
    const uint32_t b_roff = (uint32_t)(wn * 32 + b_rowl) * ROWB;

    // per-thread row scales (8 rows owned)
    float sxr[8];
#pragma unroll
    for (int mt = 0; mt < 4; ++mt)
#pragma unroll
        for (int hf = 0; hf < 2; ++hf)
            sxr[mt * 2 + hf] = g_sx[m0 + wm * 64 + mt * 16 + (L >> 2) + hf * 8];

    int acc[4][4][4];
#pragma unroll
    for (int mt = 0; mt < 4; ++mt)
#pragma unroll
        for (int nt = 0; nt < 4; ++nt)
#pragma unroll
            for (int c = 0; c < 4; ++c) acc[mt][nt][c] = 0;

    float tv1[8], tv2[8], tv3[8];
    int   tk1[8], tk2[8], tk3[8];
#pragma unroll
    for (int r = 0; r < 8; ++r) {
        tv1[r] = tv2[r] = tv3[r] = -CUDART_INF_F;
        tk1[r] = tk2[r] = tk3[r] = 0x7FFFFFFF;
    }

    for (int s = 0; s < NSTAGE; ++s) {
        if (s + 1 < NSTAGE) { load_B(Bs, s + 1, tid); CP_COMMIT(); }
        const uint32_t bstage = Bs + (uint32_t)(s & 1) * B_STAGE;

#pragma unroll
        for (int ks = 0; ks < 8; ++ks) {
            uint32_t afr[4][4];
            {
                int c = ks * 2 + a_ch;
                uint32_t swc = (uint32_t)((c & ~7) | ((c ^ a_sw) & 7)) << 4;
#pragma unroll
                for (int mt = 0; mt < 4; ++mt)
                    ldsm4(afr[mt], a_base + (uint32_t)(mt * 16) * ROWB + swc);
            }
            uint32_t bfr[2][4];
            {
                int c = ks * 2 + b_ch;
                uint32_t swc = (uint32_t)((c & ~7) | ((c ^ b_sw) & 7)) << 4;
#pragma unroll
                for (int nt2 = 0; nt2 < 2; ++nt2)
                    ldsm4(bfr[nt2], bstage + b_roff + (uint32_t)(nt2 * 16) * ROWB + swc);
            }
#pragma unroll
            for (int mt = 0; mt < 4; ++mt)
#pragma unroll
                for (int nt = 0; nt < 4; ++nt)
                    imma16832(acc[mt][nt], afr[mt], &bfr[nt >> 1][(nt & 1) * 2]);
        }

        // fold stage scores into per-thread-row top-3, reset acc
        {
            const int nb = s * CTAN + wn * 32 + (L & 3) * 2;
            float2 sh[4][2];
#pragma unroll
            for (int nt = 0; nt < 4; ++nt) {
                sh[nt][0] = g_seh[nb + nt * 8];
                sh[nt][1] = g_seh[nb + nt * 8 + 1];
            }
#pragma unroll
            for (int mt = 0; mt < 4; ++mt)
#pragma unroll
                for (int hf = 0; hf < 2; ++hf) {
                    const int rr = mt * 2 + hf;
                    const float sx = sxr[rr];
                    float v1 = tv1[rr], v2 = tv2[rr], v3 = tv3[rr];
                    int   k1 = tk1[rr], k2 = tk2[rr], k3 = tk3[rr];
#pragma unroll
                    for (int nt = 0; nt < 4; ++nt)
#pragma unroll
                        for (int cc = 0; cc < 2; ++cc) {
                            const int k = nb + nt * 8 + cc;
                            float p = (float)acc[mt][nt][hf * 2 + cc] * sh[nt][cc].x;
                            float sc = __fmaf_rn(p, sx, -sh[nt][cc].y);
                            acc[mt][nt][hf * 2 + cc] = 0;
                            if (sc > v1) {
                                v3 = v2; k3 = k2; v2 = v1; k2 = k1; v1 = sc; k1 = k;
                            } else if (sc > v2) {
                                v3 = v2; k3 = k2; v2 = sc; k2 = k;
                            } else if (sc > v3) {
                                v3 = sc; k3 = k;
                            }
                        }
                    tv1[rr] = v1; tv2[rr] = v2; tv3[rr] = v3;
                    tk1[rr] = k1; tk2[rr] = k2; tk3[rr] = k3;
                }
        }

        if (s + 1 < NSTAGE) CP_WAIT_0();
        __syncthreads();
    }

    // ---- final per-row top-8 from 16 slots x top-3 (reuse B smem area)
    float* rs = (float*)(smem + A_BYTES);                       // [128][48]
    int*   ri = (int*)(smem + A_BYTES + CTAM * 48 * 4);         // [128][48]
    const int slot = wn * 4 + (L & 3);
#pragma unroll
    for (int mt = 0; mt < 4; ++mt)
#pragma unroll
        for (int hf = 0; hf < 2; ++hf) {
            const int row = wm * 64 + mt * 16 + (L >> 2) + hf * 8;
            const int rr = mt * 2 + hf;
            rs[row * 48 + slot * 3 + 0] = tv1[rr];
            rs[row * 48 + slot * 3 + 1] = tv2[rr];
            rs[row * 48 + slot * 3 + 2] = tv3[rr];
            ri[row * 48 + slot * 3 + 0] = tk1[rr];
            ri[row * 48 + slot * 3 + 1] = tk2[rr];
            ri[row * 48 + slot * 3 + 2] = tk3[rr];
        }
    __syncthreads();
    if (tid < CTAM) {
        float v[8];
        int   id[8];
#pragma unroll
        for (int i = 0; i < 8; ++i) { v[i] = -CUDART_INF_F; id[i] = 0x7FFFFFFF; }
        for (int e = 0; e < 48; ++e) {
            float sc = rs[tid * 48 + e];
            int   k  = ri[tid * 48 + e];
            if (sc > v[7]) {
                int p = 7;
                while (p > 0 && sc > v[p - 1]) { v[p] = v[p - 1]; id[p] = id[p - 1]; --p; }
                v[p] = sc; id[p] = k;
            }
        }
        g_c8a[m0 + tid] = make_int4(id[0], id[1], id[2], id[3]);
        g_c8b[m0 + tid] = make_int4(id[4], id[5], id[6], id[7]);
    }
}

// ---------------------------------------------------------------- exact rescore (8 cands)
__global__ void rescore_kernel(const float* __restrict__ X,
                               const float* __restrict__ E,
                               float* __restrict__ idxf) {
    int w = (blockIdx.x * blockDim.x + threadIdx.x) >> 5;
    int lane = threadIdx.x & 31;
    int4 ca = g_c8a[w];
    int4 cb = g_c8b[w];
    int ks[8] = {ca.x, ca.y, ca.z, ca.w, cb.x, cb.y, cb.z, cb.w};
    const float4* x = (const float4*)(X + (size_t)w * CDIM) + lane * 2;
    float4 x0 = x[0], x1 = x[1];
    float s[8];
#pragma unroll
    for (int i = 0; i < 8; ++i) {
        const float4* e = (const float4*)(E + (size_t)ks[i] * CDIM) + lane * 2;
        float4 a = e[0], b = e[1];
        s[i] = x0.x * a.x + x0.y * a.y + x0.z * a.z + x0.w * a.w
             + x1.x * b.x + x1.y * b.y + x1.z * b.z + x1.w * b.w;
    }
#pragma unroll
    for (int o = 16; o > 0; o >>= 1)
#pragma unroll
        for (int i = 0; i < 8; ++i)
            s[i] += __shfl_xor_sync(0xFFFFFFFF, s[i], o);
    if (lane == 0) {
        float bv = s[0] - g_seh[ks[0]].y;
        int bk = ks[0];
#pragma unroll
        for (int i = 1; i < 8; ++i) {
            float sc = s[i] - g_seh[ks[i]].y;
            if (sc > bv || (sc == bv && ks[i] < bk)) { bv = sc; bk = ks[i]; }
        }
        g_idx[w] = bk;
        idxf[w] = (float)bk;
    }
}

// ---------------------------------------------------------------- gather / STE
__global__ void gather_kernel(const float* __restrict__ enc,
                              const float* __restrict__ E,
                              float* __restrict__ qflat) {
    int t = blockIdx.x * blockDim.x + threadIdx.x;
    int n = t >> 6;
    int j = t & 63;
    int idx = g_idx[n];
    float4 x = *(const float4*)(enc + (size_t)n * CDIM + j * 4);
    float4 e = *(const float4*)(E + (size_t)idx * CDIM + j * 4);
    float4 q;
    q.x = x.x + (e.x - x.x);
    q.y = x.y + (e.y - x.y);
    q.z = x.z + (e.z - x.z);
    q.w = x.w + (e.w - x.w);
    *(float4*)(qflat + (size_t)n * CDIM + j * 4) = q;
}

// ---------------------------------------------------------------- launch
extern "C" void kernel_launch(void* const* d_in, const int* in_sizes, int n_in,
                              void* d_out, int out_size) {
    const float* z   = (const float*)d_in[0];   // (16, 256, 32, 32)
    const float* emb = (const float*)d_in[1];   // (8192, 256)
    float* out   = (float*)d_out;
    float* enc   = out + OFF_ENC;
    float* qflat = out + OFF_QF;
    float* idxf  = out + OFF_IDX;
    float* quant = out + OFF_QUANT;

    cudaFuncSetAttribute(argmax_imma_kernel,
                         cudaFuncAttributeMaxDynamicSharedMemorySize, SMEM_TOTAL);

    prep_e_kernel<<<KCODES * 32 / 256, 256>>>(emb);

    dim3 tb32(32, 8);
    transpose_kernel<<<dim3(HW / 32, CDIM / 32, NB), tb32>>>(z, enc, CDIM, HW);
    prep_x_kernel<<<NPTS * 32 / 256, 256>>>(enc);

    argmax_imma_kernel<<<NPTS / CTAM, 256, SMEM_TOTAL>>>();

    rescore_kernel<<<NPTS * 32 / 256, 256>>>(enc, emb, idxf);
    gather_kernel<<<NPTS * (CDIM / 4) / 256, 256>>>(enc, emb, qflat);
    transpose_kernel<<<dim3(CDIM / 32, HW / 32, NB), tb32>>>(qflat, quant, HW, CDIM);
}

// round 9
// speedup vs baseline: 5.4438x; 1.0402x over previous
#include <cuda_runtime.h>
#include <cuda_bf16.h>
#include <math_constants.h>
#include <stdint.h>

// ---------------------------------------------------------------- constants
#define NB      16
#define CDIM    256
#define HW      1024
#define NPTS    16384
#define KCODES  8192

#define OFF_ENC   0
#define OFF_QF    (NPTS * CDIM)
#define OFF_IDX   (2 * NPTS * CDIM)
#define OFF_QUANT (2 * NPTS * CDIM + NPTS)

// int8 GEMM tiling
#define ROWB   256               // bytes per int8 row (256 k)
#define CTAM   64                // points per CTA
#define CTAN   128               // codes per stage (= n-tile)
#define NSTAGE (KCODES / CTAN)   // 64

#define A_BYTES  (CTAM * ROWB)           // 16384
#define B_STAGE  (CTAN * ROWB)           // 32768
#define SMEM_TOTAL (A_BYTES + 2 * B_STAGE)  // 81920  -> 2 CTAs/SM

__device__ int    g_idx[NPTS];
__device__ int4   g_c8a[NPTS];
__device__ int4   g_c8b[NPTS];
__device__ float  g_sx[NPTS];
__device__ float2 g_seh[KCODES];   // (se scale, 0.5*||e||^2 exact fp32)
__device__ __align__(16) int8_t g_Xq[(size_t)NPTS * CDIM];
__device__ __align__(16) int8_t g_Eq[(size_t)KCODES * CDIM];

// ---------------------------------------------------------------- helpers
__device__ __forceinline__ uint32_t smem_to_u32(const void* p) {
    uint32_t a;
    asm("{ .reg .u64 t; cvta.to.shared.u64 t, %1; cvt.u32.u64 %0, t; }" : "=r"(a) : "l"(p));
    return a;
}
__device__ __forceinline__ void cp_async16(uint32_t dst, const void* src) {
    asm volatile("cp.async.cg.shared.global [%0], [%1], 16;" :: "r"(dst), "l"(src));
}
#define CP_COMMIT() asm volatile("cp.async.commit_group;" ::: "memory")
#define CP_WAIT_0() asm volatile("cp.async.wait_group 0;" ::: "memory")

__device__ __forceinline__ void ldsm4(uint32_t* r, uint32_t addr) {
    asm volatile("ldmatrix.sync.aligned.m8n8.x4.shared.b16 {%0,%1,%2,%3}, [%4];"
                 : "=r"(r[0]), "=r"(r[1]), "=r"(r[2]), "=r"(r[3]) : "r"(addr));
}
__device__ __forceinline__ void imma16832(int* c, const uint32_t* a, const uint32_t* b) {
    asm volatile("mma.sync.aligned.m16n8k32.row.col.s32.s8.s8.s32 "
                 "{%0,%1,%2,%3}, {%4,%5,%6,%7}, {%8,%9}, {%0,%1,%2,%3};"
                 : "+r"(c[0]), "+r"(c[1]), "+r"(c[2]), "+r"(c[3])
                 : "r"(a[0]), "r"(a[1]), "r"(a[2]), "r"(a[3]),
                   "r"(b[0]), "r"(b[1]));
}
__device__ __forceinline__ uint32_t pack4(int a, int b, int c, int d) {
    return (uint32_t)(a & 255) | ((uint32_t)(b & 255) << 8)
         | ((uint32_t)(c & 255) << 16) | ((uint32_t)(d & 255) << 24);
}

// ---------------------------------------------------------------- prep kernels
__global__ void prep_e_kernel(const float* __restrict__ E) {
    int t = blockIdx.x * blockDim.x + threadIdx.x;
    int row = t >> 5, j = t & 31;                   // 8 elems per thread
    const float* p = E + (size_t)row * CDIM + j * 8;
    float4 a = *(const float4*)p;
    float4 b = *(const float4*)(p + 4);
    float v[8] = {a.x, a.y, a.z, a.w, b.x, b.y, b.z, b.w};
    float mx = 0.f, ss = 0.f;
#pragma unroll
    for (int i = 0; i < 8; ++i) { mx = fmaxf(mx, fabsf(v[i])); ss += v[i] * v[i]; }
#pragma unroll
    for (int o = 16; o > 0; o >>= 1) {
        mx = fmaxf(mx, __shfl_xor_sync(0xFFFFFFFF, mx, o));
        ss += __shfl_xor_sync(0xFFFFFFFF, ss, o);
    }
    float inv = (mx > 0.f) ? 127.f / mx : 0.f;
    int q[8];
#pragma unroll
    for (int i = 0; i < 8; ++i) q[i] = __float2int_rn(v[i] * inv);
    uint2 w;
    w.x = pack4(q[0], q[1], q[2], q[3]);
    w.y = pack4(q[4], q[5], q[6], q[7]);
    *(uint2*)(g_Eq + (size_t)row * CDIM + j * 8) = w;
    if (j == 0) g_seh[row] = make_float2(mx * (1.f / 127.f), 0.5f * ss);
}

__global__ void prep_x_kernel(const float* __restrict__ X) {
    int t = blockIdx.x * blockDim.x + threadIdx.x;
    int row = t >> 5, j = t & 31;
    const float* p = X + (size_t)row * CDIM + j * 8;
    float4 a = *(const float4*)p;
    float4 b = *(const float4*)(p + 4);
    float v[8] = {a.x, a.y, a.z, a.w, b.x, b.y, b.z, b.w};
    float mx = 0.f;
#pragma unroll
    for (int i = 0; i < 8; ++i) mx = fmaxf(mx, fabsf(v[i]));
#pragma unroll
    for (int o = 16; o > 0; o >>= 1)
        mx = fmaxf(mx, __shfl_xor_sync(0xFFFFFFFF, mx, o));
    float inv = (mx > 0.f) ? 127.f / mx : 0.f;
    int q[8];
#pragma unroll
    for (int i = 0; i < 8; ++i) q[i] = __float2int_rn(v[i] * inv);
    uint2 w;
    w.x = pack4(q[0], q[1], q[2], q[3]);
    w.y = pack4(q[4], q[5], q[6], q[7]);
    *(uint2*)(g_Xq + (size_t)row * CDIM + j * 8) = w;
    if (j == 0) g_sx[row] = mx * (1.f / 127.f);
}

__global__ void transpose_kernel(const float* __restrict__ in,
                                 float* __restrict__ out, int R, int C) {
    __shared__ float tile[32][33];
    int b  = blockIdx.z;
    int c0 = blockIdx.x * 32;
    int r0 = blockIdx.y * 32;
    const float* pin = in  + (size_t)b * R * C;
    float*       pout = out + (size_t)b * R * C;
    int tx = threadIdx.x, ty = threadIdx.y;
#pragma unroll
    for (int i = 0; i < 32; i += 8)
        tile[ty + i][tx] = pin[(size_t)(r0 + ty + i) * C + c0 + tx];
    __syncthreads();
#pragma unroll
    for (int i = 0; i < 32; i += 8)
        pout[(size_t)(c0 + ty + i) * R + r0 + tx] = tile[tx][ty + i];
}

// ---------------------------------------------------------------- stage loader
// 128 rows x 256 B; 16 chunks of 16B per row, chunk swizzle c' = (c&~7)|((c^r)&7)
__device__ __forceinline__ void load_B(uint32_t Bs, int s, int tid) {
    const int r = tid >> 1;
    const int c0 = (tid & 1) * 8;
    const char* src = (const char*)g_Eq + (size_t)(s * CTAN + r) * ROWB;
    uint32_t dst = Bs + (uint32_t)(s & 1) * B_STAGE + (uint32_t)r * ROWB;
#pragma unroll
    for (int q = 0; q < 8; ++q) {
        int c = c0 + q;
        cp_async16(dst + (uint32_t)(((c & ~7) | ((c ^ r) & 7)) << 4), src + c * 16);
    }
}

// ---------------------------------------------------------------- main kernel
// CTA: 64 points x 8192 codes; 8 warps (2m x 4n), warp tile 32x32.
// Per-thread-row top-3 with max-tree early-out; row top-8 -> exact rescore.
__global__ __launch_bounds__(256, 2)
void argmax_imma_kernel() {
    extern __shared__ char smem[];
    uint32_t As = smem_to_u32(smem);
    uint32_t Bs = As + A_BYTES;

    const int tid = threadIdx.x;
    const int wid = tid >> 5;
    const int L   = tid & 31;
    const int wm  = wid >> 2;         // 0..1  (m 32 each)
    const int wn  = wid & 3;          // 0..3  (n 32 each)
    const int m0  = blockIdx.x * CTAM;

    // ---- stage A (64 x 256 int8): 4 threads/row, 4 chunks each
    {
        const int r = tid >> 2;
        const int c0 = (tid & 3) * 4;
        const char* src = (const char*)g_Xq + (size_t)(m0 + r) * ROWB;
        uint32_t dst = As + (uint32_t)r * ROWB;
#pragma unroll
        for (int q = 0; q < 4; ++q) {
            int c = c0 + q;
            cp_async16(dst + (uint32_t)(((c & ~7) | ((c ^ r) & 7)) << 4), src + c * 16);
        }
    }
    load_B(Bs, 0, tid);
    CP_COMMIT();
    CP_WAIT_0();
    __syncthreads();

    // ldsm address components (validated recipe)
    const int a_rowl = (L & 7) + ((L >> 3) & 1) * 8;
    const uint32_t a_base = As + (uint32_t)(wm * 32 + a_rowl) * ROWB;
    const int a_sw = L & 7;
    const int a_ch = (L >> 4) & 1;

    const int b_rowl = (L & 7) + ((L >> 4) & 1) * 8;
    const int b_ch = (L >> 3) & 1;
    const int b_sw = L & 7;
    const uint32_t b_roff = (uint32_t)(wn * 32 + b_rowl) * ROWB;

    // per-thread row scales (4 rows owned: rr = mt*2 + hf)
    float sxr[4];
#pragma unroll
    for (int mt = 0; mt < 2; ++mt)
#pragma unroll
        for (int hf = 0; hf < 2; ++hf)
            sxr[mt * 2 + hf] = g_sx[m0 + wm * 32 + mt * 16 + (L >> 2) + hf * 8];

    int acc[2][4][4];
#pragma unroll
    for (int mt = 0; mt < 2; ++mt)
#pragma unroll
        for (int nt = 0; nt < 4; ++nt)
#pragma unroll
            for (int c = 0; c < 4; ++c) acc[mt][nt][c] = 0;

    float tv1[4], tv2[4], tv3[4];
    int   tk1[4], tk2[4], tk3[4];
#pragma unroll
    for (int r = 0; r < 4; ++r) {
        tv1[r] = tv2[r] = tv3[r] = -CUDART_INF_F;
        tk1[r] = tk2[r] = tk3[r] = 0x7FFFFFFF;
    }

    for (int s = 0; s < NSTAGE; ++s) {
        if (s + 1 < NSTAGE) { load_B(Bs, s + 1, tid); CP_COMMIT(); }
        const uint32_t bstage = Bs + (uint32_t)(s & 1) * B_STAGE;

#pragma unroll
        for (int ks = 0; ks < 8; ++ks) {
            uint32_t afr[2][4];
            {
                int c = ks * 2 + a_ch;
                uint32_t swc = (uint32_t)((c & ~7) | ((c ^ a_sw) & 7)) << 4;
#pragma unroll
                for (int mt = 0; mt < 2; ++mt)
                    ldsm4(afr[mt], a_base + (uint32_t)(mt * 16) * ROWB + swc);
            }
            uint32_t bfr[2][4];
            {
                int c = ks * 2 + b_ch;
                uint32_t swc = (uint32_t)((c & ~7) | ((c ^ b_sw) & 7)) << 4;
#pragma unroll
                for (int nt2 = 0; nt2 < 2; ++nt2)
                    ldsm4(bfr[nt2], bstage + b_roff + (uint32_t)(nt2 * 16) * ROWB + swc);
            }
#pragma unroll
            for (int mt = 0; mt < 2; ++mt)
#pragma unroll
                for (int nt = 0; nt < 4; ++nt)
                    imma16832(acc[mt][nt], afr[mt], &bfr[nt >> 1][(nt & 1) * 2]);
        }

        // fold stage scores: max-tree early-out, full insertion only when needed
        {
            const int nb = s * CTAN + wn * 32 + (L & 3) * 2;
            float2 sh[4][2];
#pragma unroll
            for (int nt = 0; nt < 4; ++nt) {
                sh[nt][0] = g_seh[nb + nt * 8];
                sh[nt][1] = g_seh[nb + nt * 8 + 1];
            }
#pragma unroll
            for (int mt = 0; mt < 2; ++mt)
#pragma unroll
                for (int hf = 0; hf < 2; ++hf) {
                    const int rr = mt * 2 + hf;
                    const float sx = sxr[rr];
                    float sc[8];
#pragma unroll
                    for (int nt = 0; nt < 4; ++nt)
#pragma unroll
                        for (int cc = 0; cc < 2; ++cc) {
                            float p = (float)acc[mt][nt][hf * 2 + cc] * sh[nt][cc].x;
                            sc[nt * 2 + cc] = __fmaf_rn(p, sx, -sh[nt][cc].y);
                            acc[mt][nt][hf * 2 + cc] = 0;
                        }
                    float mx = fmaxf(fmaxf(fmaxf(sc[0], sc[1]), fmaxf(sc[2], sc[3])),
                                     fmaxf(fmaxf(sc[4], sc[5]), fmaxf(sc[6], sc[7])));
                    if (mx > tv3[rr]) {          // rare: full sequential insertion
                        float v1 = tv1[rr], v2 = tv2[rr], v3 = tv3[rr];
                        int   k1 = tk1[rr], k2 = tk2[rr], k3 = tk3[rr];
#pragma unroll
                        for (int j = 0; j < 8; ++j) {
                            const float v = sc[j];
                            const int k = nb + (j >> 1) * 8 + (j & 1);
                            if (v > v1) {
                                v3 = v2; k3 = k2; v2 = v1; k2 = k1; v1 = v; k1 = k;
                            } else if (v > v2) {
                                v3 = v2; k3 = k2; v2 = v; k2 = k;
                            } else if (v > v3) {
                                v3 = v; k3 = k;
                            }
                        }
                        tv1[rr] = v1; tv2[rr] = v2; tv3[rr] = v3;
                        tk1[rr] = k1; tk2[rr] = k2; tk3[rr] = k3;
                    }
                }
        }

        if (s + 1 < NSTAGE) CP_WAIT_0();
        __syncthreads();
    }

    // ---- final per-row top-8 from 16 slots x top-3 (reuse B smem area)
    float* rs = (float*)(smem + A_BYTES);                       // [64][48]
    int*   ri = (int*)(smem + A_BYTES + CTAM * 48 * 4);         // [64][48]
    const int slot = wn * 4 + (L & 3);
#pragma unroll
    for (int mt = 0; mt < 2; ++mt)
#pragma unroll
        for (int hf = 0; hf < 2; ++hf) {
            const int row = wm * 32 + mt * 16 + (L >> 2) + hf * 8;
            const int rr = mt * 2 + hf;
            rs[row * 48 + slot * 3 + 0] = tv1[rr];
            rs[row * 48 + slot * 3 + 1] = tv2[rr];
            rs[row * 48 + slot * 3 + 2] = tv3[rr];
            ri[row * 48 + slot * 3 + 0] = tk1[rr];
            ri[row * 48 + slot * 3 + 1] = tk2[rr];
            ri[row * 48 + slot * 3 + 2] = tk3[rr];
        }
    __syncthreads();
    if (tid < CTAM) {
        float v[8];
        int   id[8];
#pragma unroll
        for (int i = 0; i < 8; ++i) { v[i] = -CUDART_INF_F; id[i] = 0x7FFFFFFF; }
        for (int e = 0; e < 48; ++e) {
            float sc = rs[tid * 48 + e];
            int   k  = ri[tid * 48 + e];
            if (sc > v[7]) {
                int p = 7;
                while (p > 0 && sc > v[p - 1]) { v[p] = v[p - 1]; id[p] = id[p - 1]; --p; }
                v[p] = sc; id[p] = k;
            }
        }
        g_c8a[m0 + tid] = make_int4(id[0], id[1], id[2], id[3]);
        g_c8b[m0 + tid] = make_int4(id[4], id[5], id[6], id[7]);
    }
}

// ---------------------------------------------------------------- exact rescore (8 cands)
__global__ void rescore_kernel(const float* __restrict__ X,
                               const float* __restrict__ E,
                               float* __restrict__ idxf) {
    int w = (blockIdx.x * blockDim.x + threadIdx.x) >> 5;
    int lane = threadIdx.x & 31;
    int4 ca = g_c8a[w];
    int4 cb = g_c8b[w];
    int ks[8] = {ca.x, ca.y, ca.z, ca.w, cb.x, cb.y, cb.z, cb.w};
    const float4* x = (const float4*)(X + (size_t)w * CDIM) + lane * 2;
    float4 x0 = x[0], x1 = x[1];
    float s[8];
#pragma unroll
    for (int i = 0; i < 8; ++i) {
        const float4* e = (const float4*)(E + (size_t)ks[i] * CDIM) + lane * 2;
        float4 a = e[0], b = e[1];
        s[i] = x0.x * a.x + x0.y * a.y + x0.z * a.z + x0.w * a.w
             + x1.x * b.x + x1.y * b.y + x1.z * b.z + x1.w * b.w;
    }
#pragma unroll
    for (int o = 16; o > 0; o >>= 1)
#pragma unroll
        for (int i = 0; i < 8; ++i)
            s[i] += __shfl_xor_sync(0xFFFFFFFF, s[i], o);
    if (lane == 0) {
        float bv = s[0] - g_seh[ks[0]].y;
        int bk = ks[0];
#pragma unroll
        for (int i = 1; i < 8; ++i) {
            float sc = s[i] - g_seh[ks[i]].y;
            if (sc > bv || (sc == bv && ks[i] < bk)) { bv = sc; bk = ks[i]; }
        }
        g_idx[w] = bk;
        idxf[w] = (float)bk;
    }
}

// ---------------------------------------------------------------- gather / STE
__global__ void gather_kernel(const float* __restrict__ enc,
                              const float* __restrict__ E,
                              float* __restrict__ qflat) {
    int t = blockIdx.x * blockDim.x + threadIdx.x;
    int n = t >> 6;
    int j = t & 63;
    int idx = g_idx[n];
    float4 x = *(const float4*)(enc + (size_t)n * CDIM + j * 4);
    float4 e = *(const float4*)(E + (size_t)idx * CDIM + j * 4);
    float4 q;
    q.x = x.x + (e.x - x.x);
    q.y = x.y + (e.y - x.y);
    q.z = x.z + (e.z - x.z);
    q.w = x.w + (e.w - x.w);
    *(float4*)(qflat + (size_t)n * CDIM + j * 4) = q;
}

// ---------------------------------------------------------------- launch
extern "C" void kernel_launch(void* const* d_in, const int* in_sizes, int n_in,
                              void* d_out, int out_size) {
    const float* z   = (const float*)d_in[0];   // (16, 256, 32, 32)
    const float* emb = (const float*)d_in[1];   // (8192, 256)
    float* out   = (float*)d_out;
    float* enc   = out + OFF_ENC;
    float* qflat = out + OFF_QF;
    float* idxf  = out + OFF_IDX;
    float* quant = out + OFF_QUANT;

    cudaFuncSetAttribute(argmax_imma_kernel,
                         cudaFuncAttributeMaxDynamicSharedMemorySize, SMEM_TOTAL);

    prep_e_kernel<<<KCODES * 32 / 256, 256>>>(emb);

    dim3 tb32(32, 8);
    transpose_kernel<<<dim3(HW / 32, CDIM / 32, NB), tb32>>>(z, enc, CDIM, HW);
    prep_x_kernel<<<NPTS * 32 / 256, 256>>>(enc);

    argmax_imma_kernel<<<NPTS / CTAM, 256, SMEM_TOTAL>>>();

    rescore_kernel<<<NPTS * 32 / 256, 256>>>(enc, emb, idxf);
    gather_kernel<<<NPTS * (CDIM / 4) / 256, 256>>>(enc, emb, qflat);
    transpose_kernel<<<dim3(CDIM / 32, HW / 32, NB), tb32>>>(qflat, quant, HW, CDIM);
}